// round 1
// baseline (speedup 1.0000x reference)
#include <cuda_runtime.h>
#include <math.h>

#define B 64
#define S 512
#define H 1024
#define L 5

#define LOG2E_F 1.4426950408889634f
#define LN2_F   0.6931471805599453f

// Scratch (static device globals — allocation-free per harness rules)
__device__ float g_emis[B * S * L];
__device__ float g_num[B];
__device__ float g_logz[B];

// ---------------------------------------------------------------------------
// Kernel 1: emissions = relu(feats @ W + b)
// Thread t owns k in [4t, 4t+4); its 20 W values live in registers.
// Each block accumulates 16 rows, then one shuffle+shared reduction.
// ---------------------------------------------------------------------------
#define ROWS_PB 16

__global__ __launch_bounds__(256) void k_emis(const float* __restrict__ feats,
                                              const float* __restrict__ W,
                                              const float* __restrict__ bias) {
    const int t = threadIdx.x;
    const int base = blockIdx.x * ROWS_PB;

    // W[k][l] row-major: thread's 20 consecutive floats start at 20*t
    float w[4][L];
    const float* wp = W + t * 20;
#pragma unroll
    for (int i = 0; i < 4; i++)
#pragma unroll
        for (int l = 0; l < L; l++) w[i][l] = wp[i * L + l];

    float acc[ROWS_PB][L];
#pragma unroll
    for (int r = 0; r < ROWS_PB; r++)
#pragma unroll
        for (int l = 0; l < L; l++) acc[r][l] = 0.f;

    const float4* fp = (const float4*)(feats + (size_t)base * H) + t;
#pragma unroll
    for (int r = 0; r < ROWS_PB; r++) {
        float4 x = fp[r * (H / 4)];
#pragma unroll
        for (int l = 0; l < L; l++)
            acc[r][l] = fmaf(x.x, w[0][l],
                        fmaf(x.y, w[1][l],
                        fmaf(x.z, w[2][l],
                        fmaf(x.w, w[3][l], acc[r][l]))));
    }

    // warp tree-reduce each of the 80 partials
#pragma unroll
    for (int r = 0; r < ROWS_PB; r++)
#pragma unroll
        for (int l = 0; l < L; l++)
#pragma unroll
            for (int d = 16; d > 0; d >>= 1)
                acc[r][l] += __shfl_xor_sync(0xffffffffu, acc[r][l], d);

    __shared__ float red[8][ROWS_PB][L];
    const int wid = t >> 5, lane = t & 31;
    if (lane == 0) {
#pragma unroll
        for (int r = 0; r < ROWS_PB; r++)
#pragma unroll
            for (int l = 0; l < L; l++) red[wid][r][l] = acc[r][l];
    }
    __syncthreads();
    if (t < ROWS_PB * L) {
        const int r = t / L, l = t % L;
        float s = bias[l];
#pragma unroll
        for (int w8 = 0; w8 < 8; w8++) s += red[w8][r][l];
        g_emis[(size_t)(base + r) * L + l] = fmaxf(s, 0.f);
    }
}

// packed [5]->[5] map composition: returns f∘g (g applied first)
__device__ __forceinline__ int fcompose(int f, int g) {
    int r = 0;
#pragma unroll
    for (int x = 0; x < 5; x++) {
        int gx = (g >> (3 * x)) & 7;
        int fx = (f >> (3 * gx)) & 7;
        r |= fx << (3 * x);
    }
    return r;
}

// ---------------------------------------------------------------------------
// Kernel 2: per-batch CRF. warp0 = forward (log Z), warp1 = Viterbi + backtrace,
// warp2 = numerator. One block per batch.
// ---------------------------------------------------------------------------
__global__ __launch_bounds__(96) void k_crf(const int* __restrict__ labels,
                                            const float* __restrict__ start_tr,
                                            const float* __restrict__ end_tr,
                                            const float* __restrict__ trans,
                                            const float* __restrict__ wts,
                                            float* __restrict__ out) {
    const int b = blockIdx.x;
    const int tid = threadIdx.x;
    const int wid = tid >> 5;
    const int lane = tid & 31;
    const float* em = g_emis + (size_t)b * (S * L);
    __shared__ int s_bp[S];

    if (wid == 0) {
        // ================= forward algorithm (prob domain, scaled) ==========
        const bool act = lane < L;
        const int j = lane;
        float E0 = 0.f, E1 = 0.f, E2 = 0.f, E3 = 0.f, E4 = 0.f;
        float p = 0.f;
        if (act) {
            E0 = expf(trans[0 * L + j]);
            E1 = expf(trans[1 * L + j]);
            E2 = expf(trans[2 * L + j]);
            E3 = expf(trans[3 * L + j]);
            E4 = expf(trans[4 * L + j]);
            p = exp2f((start_tr[j] + em[j]) * LOG2E_F);
        }
        int c = 0;

        float fb[8];
#pragma unroll
        for (int u = 0; u < 8; u++)
            fb[u] = act ? exp2f(em[(1 + u) * L + j] * LOG2E_F) : 0.f;

        for (int t0 = 1; t0 < S; t0 += 8) {
            float fn[8];
#pragma unroll
            for (int u = 0; u < 8; u++) {
                int tt = t0 + 8 + u;
                fn[u] = (act && tt < S) ? exp2f(em[tt * L + j] * LOG2E_F) : 0.f;
            }
#pragma unroll
            for (int u = 0; u < 8; u++) {
                int tcur = t0 + u;
                if (tcur < S) {
                    float p0 = __shfl_sync(0xffffffffu, p, 0);
                    float p1 = __shfl_sync(0xffffffffu, p, 1);
                    float p2 = __shfl_sync(0xffffffffu, p, 2);
                    float p3 = __shfl_sync(0xffffffffu, p, 3);
                    float p4 = __shfl_sync(0xffffffffu, p, 4);
                    float s = fmaf(p0, E0, fmaf(p1, E1, fmaf(p2, E2,
                              fmaf(p3, E3, p4 * E4))));
                    p = s * fb[u];
                }
            }
            // renormalize by 2^-k where k = exponent of max (lanes 0..7 group)
            float m = p;
            m = fmaxf(m, __shfl_xor_sync(0xffffffffu, m, 1));
            m = fmaxf(m, __shfl_xor_sync(0xffffffffu, m, 2));
            m = fmaxf(m, __shfl_xor_sync(0xffffffffu, m, 4));
            int k = ((__float_as_int(m) >> 23) & 0xff) - 127;
            p = ldexpf(p, -k);
            c += k;
#pragma unroll
            for (int u = 0; u < 8; u++) fb[u] = fn[u];
        }
        float v = act ? p * expf(end_tr[j]) : 0.f;
        v += __shfl_xor_sync(0xffffffffu, v, 1);
        v += __shfl_xor_sync(0xffffffffu, v, 2);
        v += __shfl_xor_sync(0xffffffffu, v, 4);
        if (lane == 0) g_logz[b] = (float)c * LN2_F + logf(v);
    } else if (wid == 1) {
        // ========================== Viterbi =================================
        const bool act = lane < L;
        const int j = lane;
        float T0 = 0.f, T1 = 0.f, T2 = 0.f, T3 = 0.f, T4 = 0.f;
        float v = -1e30f;
        if (act) {
            T0 = trans[0 * L + j];
            T1 = trans[1 * L + j];
            T2 = trans[2 * L + j];
            T3 = trans[3 * L + j];
            T4 = trans[4 * L + j];
            v = start_tr[j] + em[j];
        }

        float eb[8];
#pragma unroll
        for (int u = 0; u < 8; u++)
            eb[u] = act ? em[(1 + u) * L + j] : 0.f;

        for (int t0 = 1; t0 < S; t0 += 8) {
            float en[8];
#pragma unroll
            for (int u = 0; u < 8; u++) {
                int tt = t0 + 8 + u;
                en[u] = (act && tt < S) ? em[tt * L + j] : 0.f;
            }
#pragma unroll
            for (int u = 0; u < 8; u++) {
                int tcur = t0 + u;
                if (tcur < S) {
                    float v0 = __shfl_sync(0xffffffffu, v, 0);
                    float v1 = __shfl_sync(0xffffffffu, v, 1);
                    float v2 = __shfl_sync(0xffffffffu, v, 2);
                    float v3 = __shfl_sync(0xffffffffu, v, 3);
                    float v4 = __shfl_sync(0xffffffffu, v, 4);
                    float best = v0 + T0;
                    int bp = 0;
                    float cc;
                    cc = v1 + T1; if (cc > best) { best = cc; bp = 1; }
                    cc = v2 + T2; if (cc > best) { best = cc; bp = 2; }
                    cc = v3 + T3; if (cc > best) { best = cc; bp = 3; }
                    cc = v4 + T4; if (cc > best) { best = cc; bp = 4; }
                    v = act ? (best + eb[u]) : -1e30f;
                    unsigned pk = __reduce_add_sync(0xffffffffu,
                                  act ? ((unsigned)bp << (3 * j)) : 0u);
                    if (lane == 0) s_bp[tcur] = (int)pk;
                }
            }
#pragma unroll
            for (int u = 0; u < 8; u++) eb[u] = en[u];
        }

        // final tag: first-occurrence argmax over (v + end)
        float sc = act ? (v + end_tr[j]) : -1e30f;
        float s0 = __shfl_sync(0xffffffffu, sc, 0);
        float s1 = __shfl_sync(0xffffffffu, sc, 1);
        float s2 = __shfl_sync(0xffffffffu, sc, 2);
        float s3 = __shfl_sync(0xffffffffu, sc, 3);
        float s4 = __shfl_sync(0xffffffffu, sc, 4);
        int last = 0; float bb = s0;
        if (s1 > bb) { bb = s1; last = 1; }
        if (s2 > bb) { bb = s2; last = 2; }
        if (s3 > bb) { bb = s3; last = 3; }
        if (s4 > bb) { bb = s4; last = 4; }

        __syncwarp(0xffffffffu);

        // ---- backtrace via suffix scan of packed [5]->[5] map compositions
        const int IDMAP = 0 | (1 << 3) | (2 << 6) | (3 << 9) | (4 << 12);
        int wv[16];
        const int tb = lane * 16;
#pragma unroll
        for (int u = 0; u < 16; u++) wv[u] = s_bp[tb + u];
        if (lane == 0) wv[0] = IDMAP;  // M_0 does not exist

        // chunk composition: G = wv[0] ∘ wv[1] ∘ ... ∘ wv[15]
        int G = wv[0];
#pragma unroll
        for (int u = 1; u < 16; u++) G = fcompose(G, wv[u]);

        // inclusive suffix scan of G across lanes (lower lane = outermost)
        int T = G;
#pragma unroll
        for (int d = 1; d < 32; d <<= 1) {
            int o = __shfl_down_sync(0xffffffffu, T, d);
            T = (lane + d < 32) ? fcompose(T, o) : T;
        }
        int E = __shfl_down_sync(0xffffffffu, T, 1);  // exclusive suffix
        if (lane == 31) E = IDMAP;

        int tag = (E >> (3 * last)) & 7;  // path[tb+15]
        float* po = out + 1 + (size_t)b * S;
        po[tb + 15] = (float)tag;
#pragma unroll
        for (int u = 15; u >= 1; u--) {
            tag = (wv[u] >> (3 * tag)) & 7;
            po[tb + u - 1] = (float)tag;
        }
    } else {
        // ========================== numerator ===============================
        const int* lb = labels + b * S;
        float acc = 0.f;
        for (int s = lane; s < S; s += 32) {
            int l0 = lb[s];
            float term = wts[l0] * em[s * L + l0];
            if (s + 1 < S) {
                int l1 = lb[s + 1];
                term += trans[l0 * L + l1];
            }
            acc += term;
        }
#pragma unroll
        for (int d = 16; d > 0; d >>= 1)
            acc += __shfl_xor_sync(0xffffffffu, acc, d);
        if (lane == 0)
            g_num[b] = acc + start_tr[lb[0]] + end_tr[lb[S - 1]];
    }
}

// ---------------------------------------------------------------------------
// Kernel 3: loss = -sum_b(num_b - logz_b) / (B*S)
// ---------------------------------------------------------------------------
__global__ __launch_bounds__(64) void k_final(float* __restrict__ out) {
    const int t = threadIdx.x;
    float v = g_num[t] - g_logz[t];
#pragma unroll
    for (int d = 16; d > 0; d >>= 1)
        v += __shfl_xor_sync(0xffffffffu, v, d);
    __shared__ float sh[2];
    if ((t & 31) == 0) sh[t >> 5] = v;
    __syncthreads();
    if (t == 0) out[0] = -(sh[0] + sh[1]) * (1.0f / (float)(B * S));
}

// ---------------------------------------------------------------------------
// Launch. Inputs (metadata order): feats f32, labels i32, mask bool (all ones,
// unused), W_tag f32, b_tag f32, start_trans f32, end_trans f32, trans f32,
// weights f32. Output: [loss, paths(B*S)] as float32.
// ---------------------------------------------------------------------------
extern "C" void kernel_launch(void* const* d_in, const int* in_sizes, int n_in,
                              void* d_out, int out_size) {
    (void)in_sizes; (void)n_in; (void)out_size;
    const float* feats  = (const float*)d_in[0];
    const int*   labels = (const int*)d_in[1];
    const float* W      = (const float*)d_in[3];
    const float* bias   = (const float*)d_in[4];
    const float* st     = (const float*)d_in[5];
    const float* en     = (const float*)d_in[6];
    const float* tr     = (const float*)d_in[7];
    const float* wt     = (const float*)d_in[8];
    float* out = (float*)d_out;

    k_emis<<<(B * S) / ROWS_PB, 256>>>(feats, W, bias);
    k_crf<<<B, 96>>>(labels, st, en, tr, wt, out);
    k_final<<<1, 64>>>(out);
}